// round 1
// baseline (speedup 1.0000x reference)
#include <cuda_runtime.h>
#include <cuda_bf16.h>
#include <math.h>

// ---------------- problem constants ----------------
#define BB 2
#define SS 2048
#define HH 2304
#define NH 8
#define NKV 4
#define HD 256
#define FF 9216
#define MROWS (BB * SS)          // 4096
#define QC (NH * HD)             // 2048
#define KC (NKV * HD)            // 1024
#define SOFTCAP 50.0f
#define ATT_SCALE 0.0625f        // 256^-0.5
#define RMS_EPS 1e-6f

// ---------------- scratch (device globals; no allocations) ----------------
__device__ float g_h   [(size_t)MROWS * HH];
__device__ float g_q   [(size_t)MROWS * QC];
__device__ float g_k   [(size_t)MROWS * KC];
__device__ float g_v   [(size_t)MROWS * KC];
__device__ float g_sc  [(size_t)BB * NH * SS * SS];   // 256 MB
__device__ float g_o   [(size_t)MROWS * QC];
__device__ float g_attn[(size_t)MROWS * HH];
__device__ float g_h2  [(size_t)MROWS * HH];
__device__ float g_f   [(size_t)MROWS * HH];
__device__ float g_gate[(size_t)MROWS * FF];
__device__ float g_up  [(size_t)MROWS * FF];
__device__ float g_mlp [(size_t)MROWS * HH];

// ---------------- generic tiled GEMM body ----------------
// C[m,n] = sum_k A[m,k] * B(k,n)   (TB=false: B row-major [K,N]; TB=true: B is [N,K], i.e. A@B^T)
// Tiles: 128x128xK16, 256 threads, 8x8 per thread. Grid: (N/128, M/128).
template<bool TB>
__device__ __forceinline__ void gemm_body(const float* __restrict__ A,
                                          const float* __restrict__ Bm,
                                          float* __restrict__ C,
                                          int K, int lda, int ldb, int ldc) {
    __shared__ float As[16][128];
    __shared__ float Bs[16][128];

    const int m0 = blockIdx.y * 128;
    const int n0 = blockIdx.x * 128;
    const int tid = threadIdx.x;
    const int tx = tid & 15;        // 0..15 -> 8 cols each
    const int ty = tid >> 4;        // 0..15 -> 8 rows each

    float acc[8][8];
#pragma unroll
    for (int i = 0; i < 8; i++)
#pragma unroll
        for (int j = 0; j < 8; j++) acc[i][j] = 0.0f;

    for (int k0 = 0; k0 < K; k0 += 16) {
        // load A tile (128 rows x 16 k), store transposed As[k][m]
#pragma unroll
        for (int i = 0; i < 8; i++) {
            int flat = i * 256 + tid;
            int r = flat >> 4, c = flat & 15;
            As[c][r] = A[(size_t)(m0 + r) * lda + (k0 + c)];
        }
        // load B tile
#pragma unroll
        for (int i = 0; i < 8; i++) {
            int flat = i * 256 + tid;
            if (TB) {
                int r = flat >> 4, c = flat & 15;   // r = n index, c = k index
                Bs[c][r] = Bm[(size_t)(n0 + r) * ldb + (k0 + c)];
            } else {
                int r = flat >> 7, c = flat & 127;  // r = k index, c = n index
                Bs[r][c] = Bm[(size_t)(k0 + r) * ldb + (n0 + c)];
            }
        }
        __syncthreads();

#pragma unroll
        for (int kk = 0; kk < 16; kk++) {
            float a[8], b[8];
#pragma unroll
            for (int i = 0; i < 8; i++) a[i] = As[kk][ty * 8 + i];
#pragma unroll
            for (int j = 0; j < 8; j++) b[j] = Bs[kk][tx * 8 + j];
#pragma unroll
            for (int i = 0; i < 8; i++)
#pragma unroll
                for (int j = 0; j < 8; j++)
                    acc[i][j] = fmaf(a[i], b[j], acc[i][j]);
        }
        __syncthreads();
    }

#pragma unroll
    for (int i = 0; i < 8; i++) {
        float* crow = C + (size_t)(m0 + ty * 8 + i) * ldc + n0 + tx * 8;
#pragma unroll
        for (int j = 0; j < 8; j++) crow[j] = acc[i][j];
    }
}

__global__ void __launch_bounds__(256) k_gemm_nn(const float* __restrict__ A,
                                                 const float* __restrict__ Bm,
                                                 float* __restrict__ C,
                                                 int K, int lda, int ldb, int ldc) {
    gemm_body<false>(A, Bm, C, K, lda, ldb, ldc);
}

// batched QK^T: scores[bh, qi, kj] = q[b,qi,h,:]·k[b,kj,h/2,:]
__global__ void __launch_bounds__(256) k_qk() {
    int bh = blockIdx.z;
    int b = bh >> 3, h = bh & 7;
    const float* A  = g_q + (size_t)b * SS * QC + h * HD;
    const float* Bm = g_k + (size_t)b * SS * KC + (h >> 1) * HD;
    float* C = g_sc + (size_t)bh * SS * SS;
    gemm_body<true>(A, Bm, C, HD, QC, KC, SS);
}

// batched PV: o[b,qi,h,:] = sum_k p[bh,qi,k] * v[b,k,h/2,:]
__global__ void __launch_bounds__(256) k_pv() {
    int bh = blockIdx.z;
    int b = bh >> 3, h = bh & 7;
    const float* A  = g_sc + (size_t)bh * SS * SS;
    const float* Bm = g_v + (size_t)b * SS * KC + (h >> 1) * HD;
    float* C = g_o + (size_t)b * SS * QC + h * HD;
    gemm_body<false>(A, Bm, C, SS, SS, KC, QC);
}

// ---------------- rmsnorm family ----------------
__global__ void __launch_bounds__(256) k_rmsnorm(const float* __restrict__ x,
                                                 const float* __restrict__ g,
                                                 float* __restrict__ out) {
    int row = blockIdx.x;
    const float* xr = x + (size_t)row * HH;
    float s = 0.0f;
    for (int i = threadIdx.x; i < HH; i += 256) { float v = xr[i]; s = fmaf(v, v, s); }
    __shared__ float red[256];
    red[threadIdx.x] = s;
    __syncthreads();
    for (int off = 128; off > 0; off >>= 1) {
        if (threadIdx.x < off) red[threadIdx.x] += red[threadIdx.x + off];
        __syncthreads();
    }
    float rstd = rsqrtf(red[0] * (1.0f / HH) + RMS_EPS);
    float* orow = out + (size_t)row * HH;
    for (int i = threadIdx.x; i < HH; i += 256)
        orow[i] = xr[i] * rstd * (1.0f + g[i]);
}

// out = res + rmsnorm(y, g)
__global__ void __launch_bounds__(256) k_add_rms(const float* __restrict__ res,
                                                 const float* __restrict__ y,
                                                 const float* __restrict__ g,
                                                 float* __restrict__ out) {
    int row = blockIdx.x;
    const float* yr = y + (size_t)row * HH;
    float s = 0.0f;
    for (int i = threadIdx.x; i < HH; i += 256) { float v = yr[i]; s = fmaf(v, v, s); }
    __shared__ float red[256];
    red[threadIdx.x] = s;
    __syncthreads();
    for (int off = 128; off > 0; off >>= 1) {
        if (threadIdx.x < off) red[threadIdx.x] += red[threadIdx.x + off];
        __syncthreads();
    }
    float rstd = rsqrtf(red[0] * (1.0f / HH) + RMS_EPS);
    const float* rr = res + (size_t)row * HH;
    float* orow = out + (size_t)row * HH;
    for (int i = threadIdx.x; i < HH; i += 256)
        orow[i] = rr[i] + yr[i] * rstd * (1.0f + g[i]);
}

// ---------------- RoPE ----------------
// heads 0..7 = q heads, 8..11 = k heads; pair (j, j+128) per thread
__global__ void __launch_bounds__(256) k_rope() {
    int idx = blockIdx.x * 256 + threadIdx.x;            // < 4096*12*128
    int j = idx & 127;
    int hd = (idx >> 7) % 12;
    int row = idx / (12 * 128);
    int pos = row & (SS - 1);
    float inv = __powf(10000.0f, -(float)(2 * j) * (1.0f / HD));
    float fr = (float)pos * inv;
    float sn, cs;
    sincosf(fr, &sn, &cs);
    float* base = (hd < 8) ? (g_q + (size_t)row * QC + hd * HD)
                           : (g_k + (size_t)row * KC + (hd - 8) * HD);
    float v0 = base[j], v1 = base[j + 128];
    base[j]       = v0 * cs - v1 * sn;
    base[j + 128] = v1 * cs + v0 * sn;
}

// ---------------- softmax with softcap + causal mask ----------------
__global__ void __launch_bounds__(256) k_softmax() {
    int r = blockIdx.x;                 // bh*SS + qi
    int qi = r & (SS - 1);
    float* row = g_sc + (size_t)r * SS;
    int t = threadIdx.x;
    float vals[8];
    float mx = -1e30f;
#pragma unroll
    for (int i = 0; i < 8; i++) {
        int j = t + i * 256;
        float s = row[j] * ATT_SCALE;
        s = SOFTCAP * tanhf(s * (1.0f / SOFTCAP));
        if (j > qi) s -= 1e9f;
        vals[i] = s;
        mx = fmaxf(mx, s);
    }
    __shared__ float red[256];
    red[t] = mx;
    __syncthreads();
    for (int off = 128; off > 0; off >>= 1) {
        if (t < off) red[t] = fmaxf(red[t], red[t + off]);
        __syncthreads();
    }
    mx = red[0];
    __syncthreads();
    float sum = 0.0f;
#pragma unroll
    for (int i = 0; i < 8; i++) { vals[i] = __expf(vals[i] - mx); sum += vals[i]; }
    red[t] = sum;
    __syncthreads();
    for (int off = 128; off > 0; off >>= 1) {
        if (t < off) red[t] += red[t + off];
        __syncthreads();
    }
    float inv = 1.0f / red[0];
#pragma unroll
    for (int i = 0; i < 8; i++) row[t + i * 256] = vals[i] * inv;
}

// ---------------- GeGLU (tanh-approx gelu) ----------------
__global__ void __launch_bounds__(256) k_geglu() {
    int i = blockIdx.x * 256 + threadIdx.x;              // < 4096*9216
    float x = g_gate[i];
    float u = g_up[i];
    const float c0 = 0.7978845608028654f;                // sqrt(2/pi)
    float inner = c0 * fmaf(0.044715f * x * x, x, x);
    float tgt = tanhf(inner);
    g_gate[i] = 0.5f * x * (1.0f + tgt) * u;
}

// ---------------- launch ----------------
extern "C" void kernel_launch(void* const* d_in, const int* in_sizes, int n_in,
                              void* d_out, int out_size) {
    const float* x         = (const float*)d_in[0];
    // d_in[1] = mask (pure causal; applied analytically in k_softmax)
    const float* wq        = (const float*)d_in[2];
    const float* wk        = (const float*)d_in[3];
    const float* wv        = (const float*)d_in[4];
    const float* wo        = (const float*)d_in[5];
    const float* w_gate    = (const float*)d_in[6];
    const float* w_up      = (const float*)d_in[7];
    const float* w_down    = (const float*)d_in[8];
    const float* gin       = (const float*)d_in[9];
    const float* gpa       = (const float*)d_in[10];
    const float* gpf       = (const float*)d_in[11];
    const float* gpff      = (const float*)d_in[12];
    float* out = (float*)d_out;

    float *p_h, *p_q, *p_k, *p_v, *p_o, *p_attn, *p_h2, *p_f, *p_gate, *p_up, *p_mlp;
    cudaGetSymbolAddress((void**)&p_h,    g_h);
    cudaGetSymbolAddress((void**)&p_q,    g_q);
    cudaGetSymbolAddress((void**)&p_k,    g_k);
    cudaGetSymbolAddress((void**)&p_v,    g_v);
    cudaGetSymbolAddress((void**)&p_o,    g_o);
    cudaGetSymbolAddress((void**)&p_attn, g_attn);
    cudaGetSymbolAddress((void**)&p_h2,   g_h2);
    cudaGetSymbolAddress((void**)&p_f,    g_f);
    cudaGetSymbolAddress((void**)&p_gate, g_gate);
    cudaGetSymbolAddress((void**)&p_up,   g_up);
    cudaGetSymbolAddress((void**)&p_mlp,  g_mlp);

    // 1. h = rmsnorm(x, g_in)
    k_rmsnorm<<<MROWS, 256>>>(x, gin, p_h);

    // 2-4. q/k/v projections
    k_gemm_nn<<<dim3(QC / 128, MROWS / 128), 256>>>(p_h, wq, p_q, HH, HH, QC, QC);
    k_gemm_nn<<<dim3(KC / 128, MROWS / 128), 256>>>(p_h, wk, p_k, HH, HH, KC, KC);
    k_gemm_nn<<<dim3(KC / 128, MROWS / 128), 256>>>(p_h, wv, p_v, HH, HH, KC, KC);

    // 5. RoPE on q and k
    k_rope<<<(MROWS * 12 * 128) / 256, 256>>>();

    // 6. scores = q @ k^T (batched over b,h)
    k_qk<<<dim3(SS / 128, SS / 128, BB * NH), 256>>>();

    // 7. softcap + causal mask + softmax
    k_softmax<<<BB * NH * SS, 256>>>();

    // 8. o = p @ v (batched, writes [B,S,NH,HD] layout directly)
    k_pv<<<dim3(HD / 128, SS / 128, BB * NH), 256>>>();

    // 9. attn_out = o @ wo
    k_gemm_nn<<<dim3(HH / 128, MROWS / 128), 256>>>(p_o, wo, p_attn, QC, QC, HH, HH);

    // 10. h2 = x + rmsnorm(attn_out, g_post_attn)
    k_add_rms<<<MROWS, 256>>>(x, p_attn, gpa, p_h2);

    // 11. f = rmsnorm(h2, g_pre_ff)
    k_rmsnorm<<<MROWS, 256>>>(p_h2, gpf, p_f);

    // 12-13. gate/up projections
    k_gemm_nn<<<dim3(FF / 128, MROWS / 128), 256>>>(p_f, w_gate, p_gate, HH, HH, FF, FF);
    k_gemm_nn<<<dim3(FF / 128, MROWS / 128), 256>>>(p_f, w_up,   p_up,   HH, HH, FF, FF);

    // 14. gate = gelu_tanh(gate) * up
    k_geglu<<<(MROWS * FF) / 256, 256>>>();

    // 15. mlp = act @ w_down
    k_gemm_nn<<<dim3(HH / 128, MROWS / 128), 256>>>(p_gate, w_down, p_mlp, FF, FF, HH, HH);

    // 16. out = h2 + rmsnorm(mlp, g_post_ff)
    k_add_rms<<<MROWS, 256>>>(p_h2, p_mlp, gpff, out);
}

// round 2
// speedup vs baseline: 1.0003x; 1.0003x over previous
#include <cuda_runtime.h>
#include <cuda_bf16.h>
#include <math.h>

// ---------------- problem constants ----------------
#define BB 2
#define SS 2048
#define HH 2304
#define NH 8
#define NKV 4
#define HD 256
#define FF 9216
#define MROWS (BB * SS)          // 4096
#define QC (NH * HD)             // 2048
#define KC (NKV * HD)            // 1024
#define SOFTCAP 50.0f
#define ATT_SCALE 0.0625f        // 256^-0.5
#define RMS_EPS 1e-6f

// ---------------- scratch (device globals; no allocations) ----------------
__device__ float g_h   [(size_t)MROWS * HH];
__device__ float g_q   [(size_t)MROWS * QC];
__device__ float g_k   [(size_t)MROWS * KC];
__device__ float g_v   [(size_t)MROWS * KC];
__device__ float g_sc  [(size_t)BB * NH * SS * SS];   // 256 MB
__device__ float g_o   [(size_t)MROWS * QC];
__device__ float g_attn[(size_t)MROWS * HH];
__device__ float g_h2  [(size_t)MROWS * HH];
__device__ float g_f   [(size_t)MROWS * HH];
__device__ float g_gate[(size_t)MROWS * FF];
__device__ float g_up  [(size_t)MROWS * FF];
__device__ float g_mlp [(size_t)MROWS * HH];

// ---------------- generic tiled GEMM body ----------------
// C[m,n] = sum_k A[m,k] * B(k,n)   (TB=false: B row-major [K,N]; TB=true: B is [N,K], i.e. A@B^T)
// Tiles: 128x128xK16, 256 threads, 8x8 per thread. Grid: (N/128, M/128).
template<bool TB>
__device__ __forceinline__ void gemm_body(const float* __restrict__ A,
                                          const float* __restrict__ Bm,
                                          float* __restrict__ C,
                                          int K, int lda, int ldb, int ldc) {
    __shared__ float As[16][128];
    __shared__ float Bs[16][128];

    const int m0 = blockIdx.y * 128;
    const int n0 = blockIdx.x * 128;
    const int tid = threadIdx.x;
    const int tx = tid & 15;        // 0..15 -> 8 cols each
    const int ty = tid >> 4;        // 0..15 -> 8 rows each

    float acc[8][8];
#pragma unroll
    for (int i = 0; i < 8; i++)
#pragma unroll
        for (int j = 0; j < 8; j++) acc[i][j] = 0.0f;

    for (int k0 = 0; k0 < K; k0 += 16) {
        // load A tile (128 rows x 16 k), store transposed As[k][m]
#pragma unroll
        for (int i = 0; i < 8; i++) {
            int flat = i * 256 + tid;
            int r = flat >> 4, c = flat & 15;
            As[c][r] = A[(size_t)(m0 + r) * lda + (k0 + c)];
        }
        // load B tile
#pragma unroll
        for (int i = 0; i < 8; i++) {
            int flat = i * 256 + tid;
            if (TB) {
                int r = flat >> 4, c = flat & 15;   // r = n index, c = k index
                Bs[c][r] = Bm[(size_t)(n0 + r) * ldb + (k0 + c)];
            } else {
                int r = flat >> 7, c = flat & 127;  // r = k index, c = n index
                Bs[r][c] = Bm[(size_t)(k0 + r) * ldb + (n0 + c)];
            }
        }
        __syncthreads();

#pragma unroll
        for (int kk = 0; kk < 16; kk++) {
            float a[8], b[8];
#pragma unroll
            for (int i = 0; i < 8; i++) a[i] = As[kk][ty * 8 + i];
#pragma unroll
            for (int j = 0; j < 8; j++) b[j] = Bs[kk][tx * 8 + j];
#pragma unroll
            for (int i = 0; i < 8; i++)
#pragma unroll
                for (int j = 0; j < 8; j++)
                    acc[i][j] = fmaf(a[i], b[j], acc[i][j]);
        }
        __syncthreads();
    }

#pragma unroll
    for (int i = 0; i < 8; i++) {
        float* crow = C + (size_t)(m0 + ty * 8 + i) * ldc + n0 + tx * 8;
#pragma unroll
        for (int j = 0; j < 8; j++) crow[j] = acc[i][j];
    }
}

__global__ void __launch_bounds__(256) k_gemm_nn(const float* __restrict__ A,
                                                 const float* __restrict__ Bm,
                                                 float* __restrict__ C,
                                                 int K, int lda, int ldb, int ldc) {
    gemm_body<false>(A, Bm, C, K, lda, ldb, ldc);
}

// batched QK^T: scores[bh, qi, kj] = q[b,qi,h,:]·k[b,kj,h/2,:]
__global__ void __launch_bounds__(256) k_qk() {
    int bh = blockIdx.z;
    int b = bh >> 3, h = bh & 7;
    const float* A  = g_q + (size_t)b * SS * QC + h * HD;
    const float* Bm = g_k + (size_t)b * SS * KC + (h >> 1) * HD;
    float* C = g_sc + (size_t)bh * SS * SS;
    gemm_body<true>(A, Bm, C, HD, QC, KC, SS);
}

// batched PV: o[b,qi,h,:] = sum_k p[bh,qi,k] * v[b,k,h/2,:]
__global__ void __launch_bounds__(256) k_pv() {
    int bh = blockIdx.z;
    int b = bh >> 3, h = bh & 7;
    const float* A  = g_sc + (size_t)bh * SS * SS;
    const float* Bm = g_v + (size_t)b * SS * KC + (h >> 1) * HD;
    float* C = g_o + (size_t)b * SS * QC + h * HD;
    gemm_body<false>(A, Bm, C, SS, SS, KC, QC);
}

// ---------------- rmsnorm family ----------------
__global__ void __launch_bounds__(256) k_rmsnorm(const float* __restrict__ x,
                                                 const float* __restrict__ g,
                                                 float* __restrict__ out) {
    int row = blockIdx.x;
    const float* xr = x + (size_t)row * HH;
    float s = 0.0f;
    for (int i = threadIdx.x; i < HH; i += 256) { float v = xr[i]; s = fmaf(v, v, s); }
    __shared__ float red[256];
    red[threadIdx.x] = s;
    __syncthreads();
    for (int off = 128; off > 0; off >>= 1) {
        if (threadIdx.x < off) red[threadIdx.x] += red[threadIdx.x + off];
        __syncthreads();
    }
    float rstd = rsqrtf(red[0] * (1.0f / HH) + RMS_EPS);
    float* orow = out + (size_t)row * HH;
    for (int i = threadIdx.x; i < HH; i += 256)
        orow[i] = xr[i] * rstd * (1.0f + g[i]);
}

// out = res + rmsnorm(y, g)
__global__ void __launch_bounds__(256) k_add_rms(const float* __restrict__ res,
                                                 const float* __restrict__ y,
                                                 const float* __restrict__ g,
                                                 float* __restrict__ out) {
    int row = blockIdx.x;
    const float* yr = y + (size_t)row * HH;
    float s = 0.0f;
    for (int i = threadIdx.x; i < HH; i += 256) { float v = yr[i]; s = fmaf(v, v, s); }
    __shared__ float red[256];
    red[threadIdx.x] = s;
    __syncthreads();
    for (int off = 128; off > 0; off >>= 1) {
        if (threadIdx.x < off) red[threadIdx.x] += red[threadIdx.x + off];
        __syncthreads();
    }
    float rstd = rsqrtf(red[0] * (1.0f / HH) + RMS_EPS);
    const float* rr = res + (size_t)row * HH;
    float* orow = out + (size_t)row * HH;
    for (int i = threadIdx.x; i < HH; i += 256)
        orow[i] = rr[i] + yr[i] * rstd * (1.0f + g[i]);
}

// ---------------- RoPE ----------------
// heads 0..7 = q heads, 8..11 = k heads; pair (j, j+128) per thread
__global__ void __launch_bounds__(256) k_rope() {
    int idx = blockIdx.x * 256 + threadIdx.x;            // < 4096*12*128
    int j = idx & 127;
    int hd = (idx >> 7) % 12;
    int row = idx / (12 * 128);
    int pos = row & (SS - 1);
    float inv = __powf(10000.0f, -(float)(2 * j) * (1.0f / HD));
    float fr = (float)pos * inv;
    float sn, cs;
    sincosf(fr, &sn, &cs);
    float* base = (hd < 8) ? (g_q + (size_t)row * QC + hd * HD)
                           : (g_k + (size_t)row * KC + (hd - 8) * HD);
    float v0 = base[j], v1 = base[j + 128];
    base[j]       = v0 * cs - v1 * sn;
    base[j + 128] = v1 * cs + v0 * sn;
}

// ---------------- softmax with softcap + causal mask ----------------
__global__ void __launch_bounds__(256) k_softmax() {
    int r = blockIdx.x;                 // bh*SS + qi
    int qi = r & (SS - 1);
    float* row = g_sc + (size_t)r * SS;
    int t = threadIdx.x;
    float vals[8];
    float mx = -1e30f;
#pragma unroll
    for (int i = 0; i < 8; i++) {
        int j = t + i * 256;
        float s = row[j] * ATT_SCALE;
        s = SOFTCAP * tanhf(s * (1.0f / SOFTCAP));
        if (j > qi) s -= 1e9f;
        vals[i] = s;
        mx = fmaxf(mx, s);
    }
    __shared__ float red[256];
    red[t] = mx;
    __syncthreads();
    for (int off = 128; off > 0; off >>= 1) {
        if (t < off) red[t] = fmaxf(red[t], red[t + off]);
        __syncthreads();
    }
    mx = red[0];
    __syncthreads();
    float sum = 0.0f;
#pragma unroll
    for (int i = 0; i < 8; i++) { vals[i] = __expf(vals[i] - mx); sum += vals[i]; }
    red[t] = sum;
    __syncthreads();
    for (int off = 128; off > 0; off >>= 1) {
        if (t < off) red[t] += red[t + off];
        __syncthreads();
    }
    float inv = 1.0f / red[0];
#pragma unroll
    for (int i = 0; i < 8; i++) row[t + i * 256] = vals[i] * inv;
}

// ---------------- GeGLU (tanh-approx gelu) ----------------
__global__ void __launch_bounds__(256) k_geglu() {
    int i = blockIdx.x * 256 + threadIdx.x;              // < 4096*9216
    float x = g_gate[i];
    float u = g_up[i];
    const float c0 = 0.7978845608028654f;                // sqrt(2/pi)
    float inner = c0 * fmaf(0.044715f * x * x, x, x);
    float tgt = tanhf(inner);
    g_gate[i] = 0.5f * x * (1.0f + tgt) * u;
}

// ---------------- launch ----------------
extern "C" void kernel_launch(void* const* d_in, const int* in_sizes, int n_in,
                              void* d_out, int out_size) {
    const float* x         = (const float*)d_in[0];
    // d_in[1] = mask (pure causal; applied analytically in k_softmax)
    const float* wq        = (const float*)d_in[2];
    const float* wk        = (const float*)d_in[3];
    const float* wv        = (const float*)d_in[4];
    const float* wo        = (const float*)d_in[5];
    const float* w_gate    = (const float*)d_in[6];
    const float* w_up      = (const float*)d_in[7];
    const float* w_down    = (const float*)d_in[8];
    const float* gin       = (const float*)d_in[9];
    const float* gpa       = (const float*)d_in[10];
    const float* gpf       = (const float*)d_in[11];
    const float* gpff      = (const float*)d_in[12];
    float* out = (float*)d_out;

    float *p_h, *p_q, *p_k, *p_v, *p_o, *p_attn, *p_h2, *p_f, *p_gate, *p_up, *p_mlp;
    cudaGetSymbolAddress((void**)&p_h,    g_h);
    cudaGetSymbolAddress((void**)&p_q,    g_q);
    cudaGetSymbolAddress((void**)&p_k,    g_k);
    cudaGetSymbolAddress((void**)&p_v,    g_v);
    cudaGetSymbolAddress((void**)&p_o,    g_o);
    cudaGetSymbolAddress((void**)&p_attn, g_attn);
    cudaGetSymbolAddress((void**)&p_h2,   g_h2);
    cudaGetSymbolAddress((void**)&p_f,    g_f);
    cudaGetSymbolAddress((void**)&p_gate, g_gate);
    cudaGetSymbolAddress((void**)&p_up,   g_up);
    cudaGetSymbolAddress((void**)&p_mlp,  g_mlp);

    // 1. h = rmsnorm(x, g_in)
    k_rmsnorm<<<MROWS, 256>>>(x, gin, p_h);

    // 2-4. q/k/v projections
    k_gemm_nn<<<dim3(QC / 128, MROWS / 128), 256>>>(p_h, wq, p_q, HH, HH, QC, QC);
    k_gemm_nn<<<dim3(KC / 128, MROWS / 128), 256>>>(p_h, wk, p_k, HH, HH, KC, KC);
    k_gemm_nn<<<dim3(KC / 128, MROWS / 128), 256>>>(p_h, wv, p_v, HH, HH, KC, KC);

    // 5. RoPE on q and k
    k_rope<<<(MROWS * 12 * 128) / 256, 256>>>();

    // 6. scores = q @ k^T (batched over b,h)
    k_qk<<<dim3(SS / 128, SS / 128, BB * NH), 256>>>();

    // 7. softcap + causal mask + softmax
    k_softmax<<<BB * NH * SS, 256>>>();

    // 8. o = p @ v (batched, writes [B,S,NH,HD] layout directly)
    k_pv<<<dim3(HD / 128, SS / 128, BB * NH), 256>>>();

    // 9. attn_out = o @ wo
    k_gemm_nn<<<dim3(HH / 128, MROWS / 128), 256>>>(p_o, wo, p_attn, QC, QC, HH, HH);

    // 10. h2 = x + rmsnorm(attn_out, g_post_attn)
    k_add_rms<<<MROWS, 256>>>(x, p_attn, gpa, p_h2);

    // 11. f = rmsnorm(h2, g_pre_ff)
    k_rmsnorm<<<MROWS, 256>>>(p_h2, gpf, p_f);

    // 12-13. gate/up projections
    k_gemm_nn<<<dim3(FF / 128, MROWS / 128), 256>>>(p_f, w_gate, p_gate, HH, HH, FF, FF);
    k_gemm_nn<<<dim3(FF / 128, MROWS / 128), 256>>>(p_f, w_up,   p_up,   HH, HH, FF, FF);

    // 14. gate = gelu_tanh(gate) * up
    k_geglu<<<(MROWS * FF) / 256, 256>>>();

    // 15. mlp = act @ w_down
    k_gemm_nn<<<dim3(HH / 128, MROWS / 128), 256>>>(p_gate, w_down, p_mlp, FF, FF, HH, HH);

    // 16. out = h2 + rmsnorm(mlp, g_post_ff)
    k_add_rms<<<MROWS, 256>>>(p_h2, p_mlp, gpff, out);
}